// round 16
// baseline (speedup 1.0000x reference)
#include <cuda_runtime.h>
#include <cuda.h>
#include <cstdint>

// BicycleModel: B=65536 vehicles, 256 steps, 4 output planes [B,256] f32.
// R16 = R15 scaled: FOUR warps share each TMA request (BLK=128).
//  - controls: ONE TMA 2D load {16,128} (8KB) per array per chunk, SW64,
//    2 bufs, prefetch distance 2
//  - states: ONE 3D TMA store {16,128,4} (32KB) per chunk, SW64, 2 bufs,
//    wait_group.read 1
//  - smem ~97KB -> 2 blocks/SM -> 8 warps/SM (same as R15: clean test of
//    request count at fixed occupancy)

constexpr int BV  = 65536;
constexpr int NS  = 256;
constexpr int BLK = 128;           // 4 warps, 128 vehicles per block
constexpr int NCH = 16;            // chunks of 16 timesteps
constexpr int CT4 = 512;           // float4 per 128v x 16t ctrl tile (8KB)
constexpr int SB4 = 2048;          // float4 per state buffer (4p x 128v x 4)

constexpr float DT        = 0.05f;
constexpr float MAX_STEER = 0.52359877559829887f;
constexpr float MAX_SPEED = 100.0f;
constexpr float INV_WB    = 1.0f / 2.7f;

constexpr int SMEM_BYTES = 1024 + (2 * CT4 + 2 * CT4 + 2 * SB4) * 16; // 99328

__device__ __forceinline__ uint32_t s2u(const void* p) {
    uint32_t a;
    asm("{ .reg .u64 t; cvta.to.shared.u64 t, %1; cvt.u32.u64 %0, t; }"
        : "=r"(a) : "l"(p));
    return a;
}

__global__ __launch_bounds__(BLK)
void bicycle_kernel(const __grid_constant__ CUtensorMap ta,   // acc  [B,256]
                    const __grid_constant__ CUtensorMap ts,   // steer[B,256]
                    const __grid_constant__ CUtensorMap to,   // out  [4,B,256]
                    const float* __restrict__ sx,
                    const float* __restrict__ sy,
                    const float* __restrict__ syaw,
                    const float* __restrict__ ssp)
{
    extern __shared__ char smem_raw[];
    __shared__ alignas(8) unsigned long long mb[2];

    // 1024-align pool; all sub-buffers at 8KB multiples -> uniform SW64 phase.
    char* base = (char*)(((uintptr_t)smem_raw + 1023) & ~(uintptr_t)1023);
    float4* cA = (float4*)base;          // [2][512] accel tiles (8KB each)
    float4* cS = cA + 2 * CT4;           // [2][512] steer tiles
    float4* sT = cS + 2 * CT4;           // [2][2048] state bufs (32KB each)

    const int tid = threadIdx.x;
    const int vb  = blockIdx.x * BLK;
    const int b   = vb + tid;

    float x   = sx[b];
    float y   = sy[b];
    float yaw = syaw[b];
    float sp  = ssp[b];

    const uint32_t mb0u = s2u(&mb[0]);
    const uint32_t cAu  = s2u(cA);
    const uint32_t cSu  = s2u(cS);
    const uint32_t sTu  = s2u(sT);

    // SW64 swizzle: f4 column = q ^ (((base>>7) + (v>>1)) & 3).
    const int swc = (int)(((cAu >> 7) + (tid >> 1)) & 3);
    const int sws = (int)(((sTu >> 7) + (tid >> 1)) & 3);

    if (tid == 0) {
        asm volatile("mbarrier.init.shared.b64 [%0], 1;" :: "r"(mb0u)     : "memory");
        asm volatile("mbarrier.init.shared.b64 [%0], 1;" :: "r"(mb0u + 8) : "memory");
        asm volatile("fence.proxy.async.shared::cta;" ::: "memory");
    }
    __syncthreads();

    // One {16,128} load per array per chunk: 8192B each, 16384B per mbarrier.
#define ISSUE_LOAD(cc) do {                                                   \
        uint32_t mbar = mb0u + ((cc) & 1) * 8;                                \
        uint32_t da = cAu + ((cc) & 1) * (CT4 * 16);                          \
        uint32_t ds = cSu + ((cc) & 1) * (CT4 * 16);                          \
        asm volatile("mbarrier.arrive.expect_tx.shared.b64 _, [%0], %1;"      \
                     :: "r"(mbar), "r"(16384u) : "memory");                   \
        asm volatile("cp.async.bulk.tensor.2d.shared::cta.global.tile"        \
                     ".mbarrier::complete_tx::bytes [%0], [%1, {%2, %3}], [%4];" \
                     :: "r"(da), "l"(&ta), "r"((cc) * 16), "r"(vb), "r"(mbar) \
                     : "memory");                                             \
        asm volatile("cp.async.bulk.tensor.2d.shared::cta.global.tile"        \
                     ".mbarrier::complete_tx::bytes [%0], [%1, {%2, %3}], [%4];" \
                     :: "r"(ds), "l"(&ts), "r"((cc) * 16), "r"(vb), "r"(mbar) \
                     : "memory");                                             \
    } while (0)

    if (tid == 0) { ISSUE_LOAD(0); ISSUE_LOAD(1); }

#define STEP(A, ST) do {                                                     \
        float fr   = fmaf(0.01f * sp, sp, 0.1f * sp);                        \
        float spn  = fminf(fmaxf(fmaf(DT, (A) - fr, sp), 0.0f), MAX_SPEED);  \
        float sc   = fminf(fmaxf((ST), -MAX_STEER), MAX_STEER);              \
        float angv = sp * __tanf(sc) * INV_WB;                               \
        float sn, cc2;                                                       \
        __sincosf(yaw, &sn, &cc2);                                           \
        x   = fmaf(sp * cc2, DT, x);                                         \
        y   = fmaf(sp * sn, DT, y);                                          \
        yaw = fmaf(angv, DT, yaw);                                           \
        sp  = spn;                                                           \
    } while (0)

    for (int c = 0; c < NCH; ++c) {
        const int buf = c & 1;
        const int ph  = (c >> 1) & 1;

        // Wait for this chunk's control tiles (acquire) — all threads poll.
        {
            uint32_t mbar = mb0u + buf * 8;
            uint32_t done;
            asm volatile("{\n\t.reg .pred p;\n\t"
                         "mbarrier.try_wait.parity.acquire.cta.shared::cta.b64 p, [%1], %2;\n\t"
                         "selp.b32 %0, 1, 0, p;\n\t}"
                         : "=r"(done) : "r"(mbar), "r"(ph) : "memory");
            if (!done) {
                asm volatile("{\n\t.reg .pred P1;\n\t"
                             "W%=:\n\t"
                             "mbarrier.try_wait.parity.acquire.cta.shared::cta.b64 P1, [%0], %1, 0x989680;\n\t"
                             "@P1 bra.uni D%=;\n\t"
                             "bra.uni W%=;\n\t"
                             "D%=:\n\t}"
                             :: "r"(mbar), "r"(ph) : "memory");
            }
        }

        // State buffer reuse: store from chunk c-2 (same buffer) must be done
        // reading smem; tolerate one outstanding group (c-1) -> overlap.
        if (c >= 2) {
            if (tid == 0)
                asm volatile("cp.async.bulk.wait_group.read 1;" ::: "memory");
            __syncthreads();
        }

        const float4* A4p = cA + buf * CT4;
        const float4* S4p = cS + buf * CT4;
        float4* P = sT + buf * SB4;

#pragma unroll
        for (int q = 0; q < 4; ++q) {
            const int ci = tid * 4 + (q ^ swc);
            float4 A4 = A4p[ci];
            float4 S4 = S4p[ci];
            float4 X, Y, W, S;
            X.x = x; Y.x = y; W.x = yaw; S.x = sp;  STEP(A4.x, S4.x);
            X.y = x; Y.y = y; W.y = yaw; S.y = sp;  STEP(A4.y, S4.y);
            X.z = x; Y.z = y; W.z = yaw; S.z = sp;  STEP(A4.z, S4.z);
            X.w = x; Y.w = y; W.w = yaw; S.w = sp;  STEP(A4.w, S4.w);
            const int si = tid * 4 + (q ^ sws);
            P[si]        = X;           // plane 0: x
            P[512 + si]  = Y;           // plane 1: y
            P[1024 + si] = W;           // plane 2: yaw
            P[1536 + si] = S;           // plane 3: speed
        }
        __syncthreads();    // all 4 warps' STS done before thread 0 stores

        // ONE 3D TMA store {16,128,4}; then prefetch controls c+2.
        if (tid == 0) {
            asm volatile("fence.proxy.async.shared::cta;" ::: "memory");
            uint32_t src = sTu + buf * (SB4 * 16);
            asm volatile("cp.async.bulk.tensor.3d.global.shared::cta.tile.bulk_group"
                         " [%0, {%1, %2, %3}], [%4];"
                         :: "l"(&to), "r"(c * 16), "r"(vb), "r"(0), "r"(src)
                         : "memory");
            asm volatile("cp.async.bulk.commit_group;" ::: "memory");
            if (c + 2 < NCH) ISSUE_LOAD(c + 2);
        }
        __syncthreads();
    }

    if (tid == 0)
        asm volatile("cp.async.bulk.wait_group 0;" ::: "memory");
#undef STEP
#undef ISSUE_LOAD
}

// ---------------- host ----------------

typedef CUresult (*EncodeFn)(CUtensorMap*, CUtensorMapDataType, cuuint32_t, void*,
                             const cuuint64_t*, const cuuint64_t*,
                             const cuuint32_t*, const cuuint32_t*,
                             CUtensorMapInterleave, CUtensorMapSwizzle,
                             CUtensorMapL2promotion, CUtensorMapFloatOOBfill);

extern "C" void kernel_launch(void* const* d_in, const int* in_sizes, int n_in,
                              void* d_out, int out_size)
{
    (void)in_sizes; (void)n_in; (void)out_size;

    void* fptr = nullptr;
    cudaDriverEntryPointQueryResult qr;
    cudaGetDriverEntryPointByVersion("cuTensorMapEncodeTiled", &fptr, 12000,
                                     cudaEnableDefault, &qr);
    EncodeFn encode = (EncodeFn)fptr;

    CUtensorMap ta, ts, to;

    // controls: [B, 256] f32, tile 16x128, SW64 (64B rows)
    {
        cuuint64_t dims[2]    = {NS, BV};
        cuuint64_t strides[1] = {NS * 4};
        cuuint32_t box[2]     = {16, 128};
        cuuint32_t es[2]      = {1, 1};
        encode(&ta, CU_TENSOR_MAP_DATA_TYPE_FLOAT32, 2, d_in[4], dims, strides,
               box, es, CU_TENSOR_MAP_INTERLEAVE_NONE, CU_TENSOR_MAP_SWIZZLE_64B,
               CU_TENSOR_MAP_L2_PROMOTION_L2_128B, CU_TENSOR_MAP_FLOAT_OOB_FILL_NONE);
        encode(&ts, CU_TENSOR_MAP_DATA_TYPE_FLOAT32, 2, d_in[5], dims, strides,
               box, es, CU_TENSOR_MAP_INTERLEAVE_NONE, CU_TENSOR_MAP_SWIZZLE_64B,
               CU_TENSOR_MAP_L2_PROMOTION_L2_128B, CU_TENSOR_MAP_FLOAT_OOB_FILL_NONE);
    }
    // output: [4, B, 256] f32, tile 16x128x4, SW64
    {
        cuuint64_t dims[3]    = {NS, BV, 4};
        cuuint64_t strides[2] = {NS * 4, (cuuint64_t)BV * NS * 4};
        cuuint32_t box[3]     = {16, 128, 4};
        cuuint32_t es[3]      = {1, 1, 1};
        encode(&to, CU_TENSOR_MAP_DATA_TYPE_FLOAT32, 3, d_out, dims, strides,
               box, es, CU_TENSOR_MAP_INTERLEAVE_NONE, CU_TENSOR_MAP_SWIZZLE_64B,
               CU_TENSOR_MAP_L2_PROMOTION_L2_128B, CU_TENSOR_MAP_FLOAT_OOB_FILL_NONE);
    }

    cudaFuncSetAttribute(bicycle_kernel,
                         cudaFuncAttributeMaxDynamicSharedMemorySize, SMEM_BYTES);

    bicycle_kernel<<<BV / BLK, BLK, SMEM_BYTES>>>(
        ta, ts, to,
        (const float*)d_in[0], (const float*)d_in[1],
        (const float*)d_in[2], (const float*)d_in[3]);
}